// round 13
// baseline (speedup 1.0000x reference)
#include <cuda_runtime.h>
#include <cstdint>

#define B_ 32
#define T_ 64
#define D_ 32
#define H_ 256
#define Z_ 64
#define G_ 768   // 3*H
#define KP_ 128  // H_/2 (k-pairs)

typedef unsigned long long ull;

// ---------------- scratch (static device memory; no allocations) ----------------
// decoder recurrent weights, gate-split, k-quad packed:
//   g_Wr4[head][kq][j] = (r_{4kq}, r_{4kq+1}, r_{4kq+2}, r_{4kq+3})   (kq in [0,64))
__device__ float4 g_Wr4[D_ * 64 * H_ + 2 * H_];
__device__ float4 g_Wz4[D_ * 64 * H_ + 2 * H_];
__device__ float4 g_Wn4[D_ * 64 * H_ + 2 * H_];
// decoder folded input weights, gate-split, d-quad packed: [head][dq][j]
__device__ float4 g_Dr4[D_ * 8 * H_];
__device__ float4 g_Dz4[D_ * 8 * H_];
__device__ float4 g_Dn4[D_ * 8 * H_];
// encoder (layout unchanged from R11)
__device__ float4 g_Erz4[KP_ * H_ + 8 * H_];
__device__ float2 g_En2 [KP_ * H_ + 8 * H_];
__device__ float4 g_WiQ [D_ * H_ + 4 * H_];
__device__ float  g_WihT[D_ * H_ * G_];       // h_Wih transposed planar: [head][k][g]
__device__ float  g_muT [H_ * Z_];
__device__ float  g_lsT [H_ * Z_];
__device__ float  g_refcT[Z_ * H_];
__device__ float  g_h0  [B_ * H_];

// ---------------- packed f32x2 helpers ----------------
__device__ __forceinline__ void fma2(ull& d, ull a, ull b) {
    asm("fma.rn.f32x2 %0, %1, %2, %0;" : "+l"(d) : "l"(a), "l"(b));
}
__device__ __forceinline__ ull splat2(float x) {
    ull r; unsigned u = __float_as_uint(x);
    asm("mov.b64 %0, {%1, %1};" : "=l"(r) : "r"(u));
    return r;
}
__device__ __forceinline__ ull pack2(float a, float b) {
    ull r;
    asm("mov.b64 %0, {%1, %2};" : "=l"(r) : "r"(__float_as_uint(a)), "r"(__float_as_uint(b)));
    return r;
}
__device__ __forceinline__ float lo_f(ull v) { return __uint_as_float((unsigned)v); }
__device__ __forceinline__ float hi_f(ull v) { return __uint_as_float((unsigned)(v >> 32)); }
__device__ __forceinline__ float col2(ull v) { return lo_f(v) + hi_f(v); }  // even+odd collapse
__device__ __forceinline__ ull bias_lo(float b) { return (ull)__float_as_uint(b); } // (b, 0)

// ---------------- fast activations ----------------
__device__ __forceinline__ float fsigmoid(float x) {
    float e = __expf(-x);
    return __fdividef(1.f, 1.f + e);
}
__device__ __forceinline__ float ftanh(float x) {
    float e = __expf(2.f * x);
    return 1.f - __fdividef(2.f, e + 1.f);
}

// ---------------- prep: tiled transposes ----------------
// Blocks:
//   [0,512)     : h_Whh  -> g_Wr4/g_Wz4/g_Wn4 (k-quad gate-split)
//   [512,1024)  : h_Wih  -> g_WihT (planar [k][g])
//   [1024,1040) : enc_Whh-> g_Erz4/g_En2 (R11 layout)
//   [1040]      : small transposes
__global__ void __launch_bounds__(256) prep_kernel(const float* __restrict__ h_Whh,
                                                   const float* __restrict__ h_Wih,
                                                   const float* __restrict__ enc_Whh,
                                                   const float* __restrict__ enc_Wih,
                                                   const float* __restrict__ mu_w,
                                                   const float* __restrict__ ls_w,
                                                   const float* __restrict__ refc_w) {
    const int bx = blockIdx.x;
    const int tid = threadIdx.x;

    if (bx < 1040) {
        __shared__ float tile[3][64][64];   // XOR-swizzled: [g][jj][(kk+jj)&63]
        const float* src;
        int jt, kt, mode;                   // 0: decoder quad-split, 1: planar, 2: encoder R11
        int head = 0;
        if (bx < 512) {
            head = bx >> 4; jt = (bx >> 2) & 3; kt = bx & 3; mode = 0;
            src = h_Whh + (size_t)head * (G_ * H_);
        } else if (bx < 1024) {
            int e = bx - 512;
            head = e >> 4; jt = (e >> 2) & 3; kt = e & 3; mode = 1;
            src = h_Wih + (size_t)head * (G_ * H_);
        } else {
            int e = bx - 1024;
            jt = (e >> 2) & 3; kt = e & 3; mode = 2;
            src = enc_Whh;
        }
        for (int g = 0; g < 3; g++) {
            for (int i = tid; i < 64 * 64; i += 256) {
                int jj = i >> 6, kk = i & 63;
                tile[g][jj][(kk + jj) & 63] =
                    src[(size_t)(g * H_ + jt * 64 + jj) * H_ + kt * 64 + kk];
            }
        }
        __syncthreads();
        if (mode == 0) {
            for (int i = tid; i < 16 * 64; i += 256) {
                int kql = i >> 6, jj = i & 63;
                float r[4], z[4], n[4];
#pragma unroll
                for (int q = 0; q < 4; q++) {
                    int c = (4 * kql + q + jj) & 63;
                    r[q] = tile[0][jj][c]; z[q] = tile[1][jj][c]; n[q] = tile[2][jj][c];
                }
                size_t idx = (size_t)head * (64 * H_) +
                             (size_t)(kt * 16 + kql) * H_ + jt * 64 + jj;
                g_Wr4[idx] = make_float4(r[0], r[1], r[2], r[3]);
                g_Wz4[idx] = make_float4(z[0], z[1], z[2], z[3]);
                g_Wn4[idx] = make_float4(n[0], n[1], n[2], n[3]);
            }
        } else if (mode == 1) {
            for (int g = 0; g < 3; g++) {
                for (int i = tid; i < 64 * 64; i += 256) {
                    int kk = i >> 6, jj = i & 63;
                    g_WihT[(size_t)head * (H_ * G_) +
                           (size_t)(kt * 64 + kk) * G_ + g * H_ + jt * 64 + jj] =
                        tile[g][jj][(kk + jj) & 63];
                }
            }
        } else {
            for (int i = tid; i < 32 * 64; i += 256) {
                int kkp = i >> 6, jj = i & 63;
                int c0 = (2 * kkp + jj) & 63, c1 = (2 * kkp + 1 + jj) & 63;
                size_t idx = (size_t)(kt * 32 + kkp) * H_ + jt * 64 + jj;
                g_Erz4[idx] = make_float4(tile[0][jj][c0], tile[1][jj][c0],
                                          tile[0][jj][c1], tile[1][jj][c1]);
                g_En2[idx]  = make_float2(tile[2][jj][c0], tile[2][jj][c1]);
            }
        }
    } else {
        for (int i = tid; i < D_ * H_; i += 256) {
            int d = i >> 8, j = i & 255;
            g_WiQ[i] = make_float4(enc_Wih[(0 * H_ + j) * D_ + d],
                                   enc_Wih[(1 * H_ + j) * D_ + d],
                                   enc_Wih[(2 * H_ + j) * D_ + d], 0.f);
        }
        for (int i = tid; i < H_ * Z_; i += 256) {
            int k = i >> 6, z = i & 63;
            g_muT[i] = mu_w[z * H_ + k];
            g_lsT[i] = ls_w[z * H_ + k];
        }
        for (int i = tid; i < Z_ * H_; i += 256) {
            int z = i >> 8, j = i & 255;
            g_refcT[i] = refc_w[j * Z_ + z];
        }
    }
}

// ---------------- Weff folded input weights -> gate-split d-quad layout ----------------
__global__ void __launch_bounds__(256) weff_kernel(const float* __restrict__ Win) {
    const int head = blockIdx.x;
    const int g = blockIdx.y * 256 + threadIdx.x;    // blockIdx.y in [0,3)
    __shared__ float win_s[D_ * H_];                 // 32 KB
    for (int i = threadIdx.x; i < D_ * H_; i += 256)
        win_s[i] = Win[head * (D_ * H_) + i];
    __syncthreads();

    float acc[D_];
#pragma unroll
    for (int d = 0; d < D_; d++) acc[d] = 0.f;

    const float* wt = g_WihT + (size_t)head * (H_ * G_);
#pragma unroll 4
    for (int k = 0; k < H_; k++) {
        float wv = wt[(size_t)k * G_ + g];
#pragma unroll
        for (int d = 0; d < D_; d++) acc[d] += win_s[d * H_ + k] * wv;
    }
    const int gate = g >> 8, jj = g & 255;
    float* base = gate == 0 ? (float*)g_Dr4 : (gate == 1 ? (float*)g_Dz4 : (float*)g_Dn4);
#pragma unroll
    for (int d = 0; d < D_; d++)
        base[(((size_t)head * 8 + (d >> 2)) * H_ + jj) * 4 + (d & 3)] = acc[d];
}

// ---------------- encoder GRU + latent (unchanged from R11) ----------------
__global__ void __launch_bounds__(512, 1) encoder_kernel(const float* __restrict__ x_past,
                                                         const float* __restrict__ bih,
                                                         const float* __restrict__ bhh,
                                                         const float* __restrict__ eps,
                                                         const float* __restrict__ mu_b,
                                                         const float* __restrict__ ls_b,
                                                         const float* __restrict__ refc_b,
                                                         float* __restrict__ out) {
    const int b = blockIdx.x;
    const int tid = threadIdx.x;
    const int j = tid & 255;
    const int kh = tid >> 8;
    __shared__ float h_s[2][H_];
    __shared__ float x_s[D_];
    __shared__ float z_s[Z_];
    __shared__ ull xch0[256];
    __shared__ ull xch1[256];

    const float br  = bih[j] + bhh[j];
    const float bz  = bih[H_ + j] + bhh[H_ + j];
    const float bin = bih[2 * H_ + j];
    const float bhn = bhh[2 * H_ + j];

    const ulonglong2* WiQ2 = ((const ulonglong2*)g_WiQ) + (kh * 16) * H_ + j;
    const ulonglong2* wrz0 = ((const ulonglong2*)g_Erz4) + (kh * 64) * H_ + j;
    const ull*        wn0  = ((const ull*)g_En2) + (kh * 64) * H_ + j;

    float hp = 0.f;
    if (tid < 256) h_s[0][tid] = 0.f;
    int cur = 0;

    for (int t = 0; t < T_; t++) {
        __syncthreads();
        if (tid < D_) x_s[tid] = x_past[(b * T_ + t) * D_ + tid];
        __syncthreads();

        ull arz = kh ? 0ull : pack2(br, bz);
        float ain = kh ? 0.f : bin;
        float ahn = kh ? 0.f : bhn;

        {
            ulonglong2 wb[4];
#pragma unroll
            for (int i = 0; i < 4; i++) wb[i] = WiQ2[i * H_];
#pragma unroll
            for (int dd = 0; dd < 16; dd++) {
                ulonglong2 w = wb[dd & 3];
                wb[dd & 3] = WiQ2[(dd + 4) * H_];
                float xv = x_s[kh * 16 + dd];
                fma2(arz, w.x, splat2(xv));
                ain += lo_f(w.y) * xv;
            }
        }
        {
            ulonglong2 brz[8]; ull bn2[8];
#pragma unroll
            for (int i = 0; i < 8; i++) { brz[i] = wrz0[i * H_]; bn2[i] = wn0[i * H_]; }
            const ulonglong2* wpf = wrz0 + 8 * H_;
            const ull*        npf = wn0  + 8 * H_;
            const float* hrow = h_s[cur] + kh * 128;
#pragma unroll 1
            for (int kp = 0; kp < 64; kp += 8) {
#pragma unroll
                for (int u = 0; u < 8; u++) {
                    ulonglong2 w = brz[u]; ull n2 = bn2[u];
                    brz[u] = wpf[u * H_]; bn2[u] = npf[u * H_];
                    float2 h2 = *(const float2*)&hrow[(kp + u) * 2];
                    fma2(arz, w.x, splat2(h2.x));
                    fma2(arz, w.y, splat2(h2.y));
                    ahn += lo_f(n2) * h2.x;
                    ahn += hi_f(n2) * h2.y;
                }
                wpf += 8 * H_; npf += 8 * H_;
            }
        }

        if (kh == 1) { xch0[j] = arz; xch1[j] = pack2(ain, ahn); }
        __syncthreads();
        if (kh == 0) {
            ull o1 = xch0[j];
            asm("add.rn.f32x2 %0, %0, %1;" : "+l"(arz) : "l"(o1));
            ull o = xch1[j];
            ain += lo_f(o); ahn += hi_f(o);
            float r = fsigmoid(lo_f(arz));
            float u = fsigmoid(hi_f(arz));
            float n = ftanh(ain + r * ahn);
            hp = n + u * (hp - n);
            h_s[cur ^ 1][j] = hp;
        }
        cur ^= 1;
    }
    __syncthreads();

    if (tid < Z_) {
        float m = mu_b[tid], l = ls_b[tid];
#pragma unroll 8
        for (int k = 0; k < H_; k++) {
            float hv = h_s[cur][k];
            m += g_muT[k * Z_ + tid] * hv;
            l += g_lsT[k * Z_ + tid] * hv;
        }
        out[B_ * T_ * D_ + b * Z_ + tid] = m;
        out[B_ * T_ * D_ + B_ * Z_ + b * Z_ + tid] = l;
        z_s[tid] = m + eps[b * Z_ + tid] * __expf(l);
    }
    __syncthreads();

    if (tid < 256) {
        float a = refc_b[tid];
#pragma unroll 8
        for (int z = 0; z < Z_; z++) a += g_refcT[z * H_ + tid] * z_s[z];
        g_h0[b * H_ + tid] = ftanh(a);
    }
}

// ---------------- fused decoder: even/odd-k packed accumulators, zero splats ----------------
// 512 threads = (j, k-half). Each thread accumulates all 8 batches over its k-half.
// acc[gate][batch] is an f32x2 pair (even-k partial, odd-k partial); both FMA operands
// load packed straight from memory. Final = lo+hi, cross-half combine via smem.
__global__ void __launch_bounds__(512, 1) decoder_kernel(const float* __restrict__ x_past,
                                                         const float* __restrict__ x_current,
                                                         const float* __restrict__ h_bih,
                                                         const float* __restrict__ h_bhh,
                                                         const float* __restrict__ fc_w,
                                                         const float* __restrict__ fc_b,
                                                         float* __restrict__ out) {
    const int head = blockIdx.x;
    const int b0 = blockIdx.y * 8;
    const int tid = threadIdx.x;
    const int j = tid & 255;
    const int kh = tid >> 8;                     // k-half; also epilogue batch-half
    const int lane = tid & 31, warp = tid >> 5;

    __shared__ __align__(16) float h_s[8][H_];      // [batch][k] 8KB (single buffer)
    __shared__ __align__(16) float dec_s[2][8][D_]; // [buf][batch][d] 2KB
    __shared__ float xch[2][16][256];               // [half][slot][j] 32KB
    __shared__ float red_s[16][4];

    const float* bih = h_bih + head * G_;
    const float* bhh = h_bhh + head * G_;
    const float br  = bih[j] + bhh[j];
    const float bz  = bih[H_ + j] + bhh[H_ + j];
    const float bin = bih[2 * H_ + j];
    const float bhn = bhh[2 * H_ + j];
    const float fcw = fc_w[head * H_ + j];
    const float fcbv = fc_b[head];

    // my 4 epilogue batches: kh*4 .. kh*4+3
    float hp[4];
#pragma unroll
    for (int bb = 0; bb < 4; bb++) {
        hp[bb] = g_h0[(b0 + kh * 4 + bb) * H_ + j];
        h_s[kh * 4 + bb][j] = hp[bb];
    }
    // preload dec_s[0]
    if (tid < 256) {
        int b = tid >> 5, d = tid & 31;
        dec_s[0][b][d] = x_past[((b0 + b) * T_ + (T_ - 1)) * D_ + d];
    }

    const float4* Wr = g_Wr4 + (size_t)head * (64 * H_) + (kh * 32) * H_ + j;
    const float4* Wz = g_Wz4 + (size_t)head * (64 * H_) + (kh * 32) * H_ + j;
    const float4* Wn = g_Wn4 + (size_t)head * (64 * H_) + (kh * 32) * H_ + j;
    const float4* Dr = g_Dr4 + ((size_t)head * 8 + kh * 4) * H_ + j;
    const float4* Dz = g_Dz4 + ((size_t)head * 8 + kh * 4) * H_ + j;
    const float4* Dn = g_Dn4 + ((size_t)head * 8 + kh * 4) * H_ + j;
    const int obh = 1 - kh;

    __syncthreads();

    for (int t = 0; t < T_; t++) {
        const int tb = t & 1;
        ull ar[8], az[8], an[8];
#pragma unroll
        for (int b = 0; b < 8; b++) {
            ar[b] = kh ? 0ull : bias_lo(br);
            az[b] = kh ? 0ull : bias_lo(bz);
            an[b] = kh ? 0ull : bias_lo(bin);   // d-phase: an holds gi n-part
        }

        // ---- gi phase: 4 d-quads, operands packed (no splats) ----
#pragma unroll
        for (int dq = 0; dq < 4; dq++) {
            ulonglong2 wr = *(const ulonglong2*)(Dr + dq * H_);
            ulonglong2 wz = *(const ulonglong2*)(Dz + dq * H_);
            ulonglong2 wn = *(const ulonglong2*)(Dn + dq * H_);
            const float* xb = &dec_s[tb][0][kh * 16 + dq * 4];
#pragma unroll
            for (int b = 0; b < 8; b++) {
                ulonglong2 x2 = *(const ulonglong2*)(xb + b * D_);
                fma2(ar[b], wr.x, x2.x); fma2(ar[b], wr.y, x2.y);
                fma2(az[b], wz.x, x2.x); fma2(az[b], wz.y, x2.y);
                fma2(an[b], wn.x, x2.x); fma2(an[b], wn.y, x2.y);
            }
        }
        // collapse gi n-part, reset an for recurrent phase
        float ainf[8];
#pragma unroll
        for (int b = 0; b < 8; b++) {
            ainf[b] = col2(an[b]);
            an[b] = kh ? 0ull : bias_lo(bhn);
        }

        // ---- gh phase: 32 k-quads, double-buffered, zero splats ----
        {
            ulonglong2 wr[2], wz[2], wn[2];
            wr[0] = *(const ulonglong2*)Wr;        wr[1] = *(const ulonglong2*)(Wr + H_);
            wz[0] = *(const ulonglong2*)Wz;        wz[1] = *(const ulonglong2*)(Wz + H_);
            wn[0] = *(const ulonglong2*)Wn;        wn[1] = *(const ulonglong2*)(Wn + H_);
            const float* hb = &h_s[0][kh * 128];
#pragma unroll 4
            for (int kq = 0; kq < 32; kq++) {
                const int s = kq & 1;
                ulonglong2 cwr = wr[s], cwz = wz[s], cwn = wn[s];
                wr[s] = *(const ulonglong2*)(Wr + (kq + 2) * H_);  // pad covers overrun
                wz[s] = *(const ulonglong2*)(Wz + (kq + 2) * H_);
                wn[s] = *(const ulonglong2*)(Wn + (kq + 2) * H_);
                const float* hk = hb + kq * 4;
#pragma unroll
                for (int b = 0; b < 8; b++) {
                    ulonglong2 h2 = *(const ulonglong2*)(hk + b * H_);
                    fma2(ar[b], cwr.x, h2.x); fma2(ar[b], cwr.y, h2.y);
                    fma2(az[b], cwz.x, h2.x); fma2(az[b], cwz.y, h2.y);
                    fma2(an[b], cwn.x, h2.x); fma2(an[b], cwn.y, h2.y);
                }
            }
        }

        // load next decoder input (overlaps with exchange)
        float vnext = 0.f;
        if (tid < 256 && t + 1 < T_) {
            int b = tid >> 5, d = tid & 31;
            vnext = x_current[((b0 + b) * T_ + t) * D_ + d];
        }

        // ---- exchange: collapsed partials for the other half's 4 batches ----
#pragma unroll
        for (int i = 0; i < 4; i++) {
            int b = obh * 4 + i;
            xch[kh][i][j]      = col2(ar[b]);
            xch[kh][4 + i][j]  = col2(az[b]);
            xch[kh][8 + i][j]  = col2(an[b]);
            xch[kh][12 + i][j] = ainf[b];
        }
        __syncthreads();

        // ---- combine + epilogue for my 4 batches ----
        float p[4];
#pragma unroll
        for (int i = 0; i < 4; i++) {
            int b = kh * 4 + i;
            float arf = col2(ar[b]) + xch[obh][i][j];
            float azf = col2(az[b]) + xch[obh][4 + i][j];
            float anf = col2(an[b]) + xch[obh][8 + i][j];
            float aif = ainf[b] + xch[obh][12 + i][j];
            float r = fsigmoid(arf);
            float u = fsigmoid(azf);
            float n = ftanh(aif + r * anf);
            float hn = n + u * (hp[i] - n);
            hp[i] = hn;
            h_s[b][j] = hn;
            p[i] = fcw * hn;
        }
        if (tid < 256 && t + 1 < T_) {
            int b = tid >> 5, d = tid & 31;
            dec_s[tb ^ 1][b][d] = vnext;
        }

        // fc reduction
#pragma unroll
        for (int i = 0; i < 4; i++) {
#pragma unroll
            for (int off = 16; off > 0; off >>= 1)
                p[i] += __shfl_down_sync(0xffffffffu, p[i], off);
        }
        if (lane == 0) {
#pragma unroll
            for (int i = 0; i < 4; i++) red_s[warp][i] = p[i];
        }
        __syncthreads();
        if (tid < 8) {
            int w0 = (tid < 4) ? 0 : 8;
            int col = tid & 3;
            float s = fcbv;
#pragma unroll
            for (int w = 0; w < 8; w++) s += red_s[w0 + w][col];
            out[((b0 + tid) * T_ + t) * D_ + head] = s;
        }
    }
}

// ---------------- launch ----------------
extern "C" void kernel_launch(void* const* d_in, const int* in_sizes, int n_in,
                              void* d_out, int out_size) {
    (void)in_sizes; (void)n_in; (void)out_size;
    const float* x_past    = (const float*)d_in[0];
    const float* x_current = (const float*)d_in[1];
    const float* eps       = (const float*)d_in[2];
    const float* enc_Wih   = (const float*)d_in[3];
    const float* enc_bih   = (const float*)d_in[4];
    const float* enc_Whh   = (const float*)d_in[5];
    const float* enc_bhh   = (const float*)d_in[6];
    const float* enc_mu_w  = (const float*)d_in[7];
    const float* enc_mu_b  = (const float*)d_in[8];
    const float* enc_ls_w  = (const float*)d_in[9];
    const float* enc_ls_b  = (const float*)d_in[10];
    const float* refc_w    = (const float*)d_in[11];
    const float* refc_b    = (const float*)d_in[12];
    const float* Win       = (const float*)d_in[13];
    const float* h_Wih     = (const float*)d_in[14];
    const float* h_bih     = (const float*)d_in[15];
    const float* h_Whh     = (const float*)d_in[16];
    const float* h_bhh     = (const float*)d_in[17];
    const float* fc_w      = (const float*)d_in[18];
    const float* fc_b      = (const float*)d_in[19];
    float* out = (float*)d_out;

    prep_kernel<<<1041, 256>>>(h_Whh, h_Wih, enc_Whh, enc_Wih, enc_mu_w, enc_ls_w, refc_w);
    weff_kernel<<<dim3(32, 3), 256>>>(Win);
    encoder_kernel<<<32, 512>>>(x_past, enc_bih, enc_bhh, eps, enc_mu_b, enc_ls_b,
                                refc_b, out);
    decoder_kernel<<<dim3(32, 4), 512>>>(x_past, x_current, h_bih, h_bhh,
                                         fc_w, fc_b, out);
}

// round 16
// speedup vs baseline: 1.5955x; 1.5955x over previous
#include <cuda_runtime.h>
#include <cstdint>

#define B_ 32
#define T_ 64
#define D_ 32
#define H_ 256
#define Z_ 64
#define G_ 768   // 3*H
#define KP_ 128  // H_/2 (k-pairs)

typedef unsigned long long ull;

// ---------------- scratch (static device memory; no allocations) ----------------
// decoder recurrent weights, gate-split, k-quad packed:
//   g_Wr4[head][kq][j] = (r_{4kq}, r_{4kq+1}, r_{4kq+2}, r_{4kq+3})   (kq in [0,64))
__device__ float4 g_Wr4[D_ * 64 * H_ + 2 * H_];
__device__ float4 g_Wz4[D_ * 64 * H_ + 2 * H_];
__device__ float4 g_Wn4[D_ * 64 * H_ + 2 * H_];
// decoder folded input weights, gate-split, d-quad packed: [head][dq][j]
__device__ float4 g_Dr4[D_ * 8 * H_];
__device__ float4 g_Dz4[D_ * 8 * H_];
__device__ float4 g_Dn4[D_ * 8 * H_];
// encoder recurrent, k-paired (r,z) + n-split
__device__ float4 g_Erz4[KP_ * H_ + 8 * H_];
__device__ float2 g_En2 [KP_ * H_ + 8 * H_];
__device__ float4 g_WiQ [D_ * H_ + 4 * H_];
__device__ float  g_WihT[D_ * H_ * G_];       // h_Wih transposed planar: [head][k][g]
__device__ float  g_muT [H_ * Z_];
__device__ float  g_lsT [H_ * Z_];
__device__ float  g_refcT[Z_ * H_];
__device__ float  g_h0  [B_ * H_];

// ---------------- packed f32x2 helpers ----------------
__device__ __forceinline__ void fma2(ull& d, ull a, ull b) {
    asm("fma.rn.f32x2 %0, %1, %2, %0;" : "+l"(d) : "l"(a), "l"(b));
}
__device__ __forceinline__ void add2(ull& d, ull a) {
    asm("add.rn.f32x2 %0, %0, %1;" : "+l"(d) : "l"(a));
}
__device__ __forceinline__ ull splat2(float x) {
    ull r; unsigned u = __float_as_uint(x);
    asm("mov.b64 %0, {%1, %1};" : "=l"(r) : "r"(u));
    return r;
}
__device__ __forceinline__ ull pack2(float a, float b) {
    ull r;
    asm("mov.b64 %0, {%1, %2};" : "=l"(r) : "r"(__float_as_uint(a)), "r"(__float_as_uint(b)));
    return r;
}
__device__ __forceinline__ float lo_f(ull v) { return __uint_as_float((unsigned)v); }
__device__ __forceinline__ float hi_f(ull v) { return __uint_as_float((unsigned)(v >> 32)); }
__device__ __forceinline__ float col2(ull v) { return lo_f(v) + hi_f(v); }  // even+odd collapse
__device__ __forceinline__ ull bias_lo(float b) { return (ull)__float_as_uint(b); } // (b, 0)

// ---------------- fast activations ----------------
__device__ __forceinline__ float fsigmoid(float x) {
    float e = __expf(-x);
    return __fdividef(1.f, 1.f + e);
}
__device__ __forceinline__ float ftanh(float x) {
    float e = __expf(2.f * x);
    return 1.f - __fdividef(2.f, e + 1.f);
}

// ---------------- prep: tiled transposes (unchanged, proven) ----------------
__global__ void __launch_bounds__(256) prep_kernel(const float* __restrict__ h_Whh,
                                                   const float* __restrict__ h_Wih,
                                                   const float* __restrict__ enc_Whh,
                                                   const float* __restrict__ enc_Wih,
                                                   const float* __restrict__ mu_w,
                                                   const float* __restrict__ ls_w,
                                                   const float* __restrict__ refc_w) {
    const int bx = blockIdx.x;
    const int tid = threadIdx.x;

    if (bx < 1040) {
        __shared__ float tile[3][64][64];   // XOR-swizzled: [g][jj][(kk+jj)&63]
        const float* src;
        int jt, kt, mode;                   // 0: decoder quad-split, 1: planar, 2: encoder
        int head = 0;
        if (bx < 512) {
            head = bx >> 4; jt = (bx >> 2) & 3; kt = bx & 3; mode = 0;
            src = h_Whh + (size_t)head * (G_ * H_);
        } else if (bx < 1024) {
            int e = bx - 512;
            head = e >> 4; jt = (e >> 2) & 3; kt = e & 3; mode = 1;
            src = h_Wih + (size_t)head * (G_ * H_);
        } else {
            int e = bx - 1024;
            jt = (e >> 2) & 3; kt = e & 3; mode = 2;
            src = enc_Whh;
        }
        for (int g = 0; g < 3; g++) {
            for (int i = tid; i < 64 * 64; i += 256) {
                int jj = i >> 6, kk = i & 63;
                tile[g][jj][(kk + jj) & 63] =
                    src[(size_t)(g * H_ + jt * 64 + jj) * H_ + kt * 64 + kk];
            }
        }
        __syncthreads();
        if (mode == 0) {
            for (int i = tid; i < 16 * 64; i += 256) {
                int kql = i >> 6, jj = i & 63;
                float r[4], z[4], n[4];
#pragma unroll
                for (int q = 0; q < 4; q++) {
                    int c = (4 * kql + q + jj) & 63;
                    r[q] = tile[0][jj][c]; z[q] = tile[1][jj][c]; n[q] = tile[2][jj][c];
                }
                size_t idx = (size_t)head * (64 * H_) +
                             (size_t)(kt * 16 + kql) * H_ + jt * 64 + jj;
                g_Wr4[idx] = make_float4(r[0], r[1], r[2], r[3]);
                g_Wz4[idx] = make_float4(z[0], z[1], z[2], z[3]);
                g_Wn4[idx] = make_float4(n[0], n[1], n[2], n[3]);
            }
        } else if (mode == 1) {
            for (int g = 0; g < 3; g++) {
                for (int i = tid; i < 64 * 64; i += 256) {
                    int kk = i >> 6, jj = i & 63;
                    g_WihT[(size_t)head * (H_ * G_) +
                           (size_t)(kt * 64 + kk) * G_ + g * H_ + jt * 64 + jj] =
                        tile[g][jj][(kk + jj) & 63];
                }
            }
        } else {
            for (int i = tid; i < 32 * 64; i += 256) {
                int kkp = i >> 6, jj = i & 63;
                int c0 = (2 * kkp + jj) & 63, c1 = (2 * kkp + 1 + jj) & 63;
                size_t idx = (size_t)(kt * 32 + kkp) * H_ + jt * 64 + jj;
                g_Erz4[idx] = make_float4(tile[0][jj][c0], tile[1][jj][c0],
                                          tile[0][jj][c1], tile[1][jj][c1]);
                g_En2[idx]  = make_float2(tile[2][jj][c0], tile[2][jj][c1]);
            }
        }
    } else {
        for (int i = tid; i < D_ * H_; i += 256) {
            int d = i >> 8, j = i & 255;
            g_WiQ[i] = make_float4(enc_Wih[(0 * H_ + j) * D_ + d],
                                   enc_Wih[(1 * H_ + j) * D_ + d],
                                   enc_Wih[(2 * H_ + j) * D_ + d], 0.f);
        }
        for (int i = tid; i < H_ * Z_; i += 256) {
            int k = i >> 6, z = i & 63;
            g_muT[i] = mu_w[z * H_ + k];
            g_lsT[i] = ls_w[z * H_ + k];
        }
        for (int i = tid; i < Z_ * H_; i += 256) {
            int z = i >> 8, j = i & 255;
            g_refcT[i] = refc_w[j * Z_ + z];
        }
    }
}

// ---------------- Weff folded input weights -> gate-split d-quad layout ----------------
__global__ void __launch_bounds__(256) weff_kernel(const float* __restrict__ Win) {
    const int head = blockIdx.x;
    const int g = blockIdx.y * 256 + threadIdx.x;    // blockIdx.y in [0,3)
    __shared__ float win_s[D_ * H_];                 // 32 KB
    for (int i = threadIdx.x; i < D_ * H_; i += 256)
        win_s[i] = Win[head * (D_ * H_) + i];
    __syncthreads();

    float acc[D_];
#pragma unroll
    for (int d = 0; d < D_; d++) acc[d] = 0.f;

    const float* wt = g_WihT + (size_t)head * (H_ * G_);
#pragma unroll 4
    for (int k = 0; k < H_; k++) {
        float wv = wt[(size_t)k * G_ + g];
#pragma unroll
        for (int d = 0; d < D_; d++) acc[d] += win_s[d * H_ + k] * wv;
    }
    const int gate = g >> 8, jj = g & 255;
    float* base = gate == 0 ? (float*)g_Dr4 : (gate == 1 ? (float*)g_Dz4 : (float*)g_Dn4);
#pragma unroll
    for (int d = 0; d < D_; d++)
        base[(((size_t)head * 8 + (d >> 2)) * H_ + jj) * 4 + (d & 3)] = acc[d];
}

// ---------------- encoder GRU + latent: one CTA per batch, 1024 threads (j x k-quarter) ----------------
__global__ void __launch_bounds__(1024, 1) encoder_kernel(const float* __restrict__ x_past,
                                                          const float* __restrict__ bih,
                                                          const float* __restrict__ bhh,
                                                          const float* __restrict__ eps,
                                                          const float* __restrict__ mu_b,
                                                          const float* __restrict__ ls_b,
                                                          const float* __restrict__ refc_b,
                                                          float* __restrict__ out) {
    const int b = blockIdx.x;
    const int tid = threadIdx.x;
    const int j = tid & 255;
    const int kq = tid >> 8;               // k-quarter in [0,4)
    __shared__ float h_s[H_];              // single buffer (sync-protected)
    __shared__ float x_s[D_];
    __shared__ float z_s[Z_];
    __shared__ ull xa[3][256];             // quarters 1..3: arz partial
    __shared__ ull xb_[3][256];            // quarters 1..3: (ain, ahn) partial

    const float br  = bih[j] + bhh[j];
    const float bz  = bih[H_ + j] + bhh[H_ + j];
    const float bin = bih[2 * H_ + j];
    const float bhn = bhh[2 * H_ + j];

    const ulonglong2* WiQ2 = ((const ulonglong2*)g_WiQ) + (kq * 8) * H_ + j;
    const ulonglong2* wrz0 = ((const ulonglong2*)g_Erz4) + (kq * 32) * H_ + j;
    const ull*        wn0  = ((const ull*)g_En2) + (kq * 32) * H_ + j;

    float hp = 0.f;
    if (tid < 256) h_s[tid] = 0.f;
    if (tid < D_)  x_s[tid] = x_past[(b * T_) * D_ + tid];
    __syncthreads();

    for (int t = 0; t < T_; t++) {
        ull arz = kq ? 0ull : pack2(br, bz);
        float ain = kq ? 0.f : bin;
        float ahn = kq ? 0.f : bhn;

        // gi: 8 local d iters
#pragma unroll
        for (int dd = 0; dd < 8; dd++) {
            ulonglong2 w = WiQ2[dd * H_];
            float xv = x_s[kq * 8 + dd];
            fma2(arz, w.x, splat2(xv));
            ain += lo_f(w.y) * xv;
        }

        // gh: 32 local k-pairs, prefetch depth 4
        {
            ulonglong2 brz[4]; ull bn2[4];
#pragma unroll
            for (int i = 0; i < 4; i++) { brz[i] = wrz0[i * H_]; bn2[i] = wn0[i * H_]; }
            const ulonglong2* wpf = wrz0 + 4 * H_;
            const ull*        npf = wn0  + 4 * H_;
            const float* hrow = h_s + kq * 64;
#pragma unroll 1
            for (int kp = 0; kp < 32; kp += 4) {
#pragma unroll
                for (int u = 0; u < 4; u++) {
                    ulonglong2 w = brz[u]; ull n2 = bn2[u];
                    brz[u] = wpf[u * H_]; bn2[u] = npf[u * H_];   // pad covers overrun
                    float2 h2 = *(const float2*)&hrow[(kp + u) * 2];
                    fma2(arz, w.x, splat2(h2.x));
                    fma2(arz, w.y, splat2(h2.y));
                    ahn += lo_f(n2) * h2.x;
                    ahn += hi_f(n2) * h2.y;
                }
                wpf += 4 * H_; npf += 4 * H_;
            }
        }

        if (kq > 0) { xa[kq - 1][j] = arz; xb_[kq - 1][j] = pack2(ain, ahn); }
        float xv_n = 0.f;
        if (tid < D_ && t + 1 < T_) xv_n = x_past[(b * T_ + t + 1) * D_ + tid];
        __syncthreads();                                  // A: partials ready

        if (kq == 0) {
#pragma unroll
            for (int q = 0; q < 3; q++) {
                add2(arz, xa[q][j]);
                ull o = xb_[q][j];
                ain += lo_f(o); ahn += hi_f(o);
            }
            float r = fsigmoid(lo_f(arz));
            float u = fsigmoid(hi_f(arz));
            float n = ftanh(ain + r * ahn);
            hp = n + u * (hp - n);
            h_s[j] = hp;
        }
        if (tid < D_ && t + 1 < T_) x_s[tid] = xv_n;
        __syncthreads();                                  // B: h_s/x_s(t+1) ready
    }

    // --- latent: mu/logsig/z/h0 ---
    if (tid < Z_) {
        float m = mu_b[tid], l = ls_b[tid];
#pragma unroll 8
        for (int k = 0; k < H_; k++) {
            float hv = h_s[k];
            m += g_muT[k * Z_ + tid] * hv;
            l += g_lsT[k * Z_ + tid] * hv;
        }
        out[B_ * T_ * D_ + b * Z_ + tid] = m;
        out[B_ * T_ * D_ + B_ * Z_ + b * Z_ + tid] = l;
        z_s[tid] = m + eps[b * Z_ + tid] * __expf(l);
    }
    __syncthreads();

    if (tid < 256) {
        float a = refc_b[tid];
#pragma unroll 8
        for (int z = 0; z < Z_; z++) a += g_refcT[z * H_ + tid] * z_s[z];
        g_h0[b * H_ + tid] = ftanh(a);
    }
}

// ---------------- fused decoder: even/odd-k packed, register-dieted, 2 barriers/step ----------------
// 512 threads = (j, k-half). gh phase FIRST (an holds h_n part, bias bhn), collapse,
// then gi phase reuses the an slots for i_n (bias bin). No ainf/hp register overlap.
__global__ void __launch_bounds__(512, 1) decoder_kernel(const float* __restrict__ x_past,
                                                         const float* __restrict__ x_current,
                                                         const float* __restrict__ h_bih,
                                                         const float* __restrict__ h_bhh,
                                                         const float* __restrict__ fc_w,
                                                         const float* __restrict__ fc_b,
                                                         float* __restrict__ out) {
    const int head = blockIdx.x;
    const int b0 = blockIdx.y * 8;
    const int tid = threadIdx.x;
    const int j = tid & 255;
    const int kh = tid >> 8;                     // k-half; also epilogue batch-half
    const int lane = tid & 31, warp = tid >> 5;

    __shared__ __align__(16) float h_s[8][H_];      // [batch][k] 8KB (single buffer)
    __shared__ __align__(16) float dec_s[2][8][D_]; // [buf][batch][d] 2KB
    __shared__ float xch[2][16][256];               // [half][slot][j] 32KB
    __shared__ float red_s[16][4];

    const float* bih = h_bih + head * G_;
    const float* bhh = h_bhh + head * G_;
    const float br  = bih[j] + bhh[j];
    const float bz  = bih[H_ + j] + bhh[H_ + j];
    const float bin = bih[2 * H_ + j];
    const float bhn = bhh[2 * H_ + j];
    const float fcw = fc_w[head * H_ + j];
    const float fcbv = fc_b[head];

#pragma unroll
    for (int bb = 0; bb < 4; bb++)
        h_s[kh * 4 + bb][j] = g_h0[(b0 + kh * 4 + bb) * H_ + j];
    if (tid < 256) {
        int b = tid >> 5, d = tid & 31;
        dec_s[0][b][d] = x_past[((b0 + b) * T_ + (T_ - 1)) * D_ + d];
    }

    const float4* Wr = g_Wr4 + (size_t)head * (64 * H_) + (kh * 32) * H_ + j;
    const float4* Wz = g_Wz4 + (size_t)head * (64 * H_) + (kh * 32) * H_ + j;
    const float4* Wn = g_Wn4 + (size_t)head * (64 * H_) + (kh * 32) * H_ + j;
    const int obh = 1 - kh;

    __syncthreads();

    for (int t = 0; t < T_; t++) {
        const int tb = t & 1;
        ull ar[8], az[8], an[8];
#pragma unroll
        for (int b = 0; b < 8; b++) {
            ar[b] = kh ? 0ull : bias_lo(br);
            az[b] = kh ? 0ull : bias_lo(bz);
            an[b] = kh ? 0ull : bias_lo(bhn);   // gh phase: an = h_n part
        }

        // ---- gh phase: 32 k-quads, double-buffered, zero splats ----
        {
            ulonglong2 wr[2], wz[2], wn[2];
            wr[0] = *(const ulonglong2*)Wr;        wr[1] = *(const ulonglong2*)(Wr + H_);
            wz[0] = *(const ulonglong2*)Wz;        wz[1] = *(const ulonglong2*)(Wz + H_);
            wn[0] = *(const ulonglong2*)Wn;        wn[1] = *(const ulonglong2*)(Wn + H_);
            const float* hb = &h_s[0][kh * 128];
#pragma unroll 4
            for (int kq = 0; kq < 32; kq++) {
                const int s = kq & 1;
                ulonglong2 cwr = wr[s], cwz = wz[s], cwn = wn[s];
                wr[s] = *(const ulonglong2*)(Wr + (kq + 2) * H_);  // pad covers overrun
                wz[s] = *(const ulonglong2*)(Wz + (kq + 2) * H_);
                wn[s] = *(const ulonglong2*)(Wn + (kq + 2) * H_);
                const float* hk = hb + kq * 4;
#pragma unroll
                for (int b = 0; b < 8; b++) {
                    ulonglong2 h2 = *(const ulonglong2*)(hk + b * H_);
                    fma2(ar[b], cwr.x, h2.x); fma2(ar[b], cwr.y, h2.y);
                    fma2(az[b], cwz.x, h2.x); fma2(az[b], cwz.y, h2.y);
                    fma2(an[b], cwn.x, h2.x); fma2(an[b], cwn.y, h2.y);
                }
            }
        }

        // collapse h_n part; reuse an slots for gi i_n part
        float anf[8];
#pragma unroll
        for (int b = 0; b < 8; b++) {
            anf[b] = col2(an[b]);
            an[b] = kh ? 0ull : bias_lo(bin);
        }

        // ---- gi phase: 4 d-quads (weights loaded in-scope, no long-lived ptrs) ----
        {
            const float4* Dr = g_Dr4 + ((size_t)head * 8 + kh * 4) * H_ + j;
            const float4* Dz = g_Dz4 + ((size_t)head * 8 + kh * 4) * H_ + j;
            const float4* Dn = g_Dn4 + ((size_t)head * 8 + kh * 4) * H_ + j;
#pragma unroll
            for (int dq = 0; dq < 4; dq++) {
                ulonglong2 wr = *(const ulonglong2*)(Dr + dq * H_);
                ulonglong2 wz = *(const ulonglong2*)(Dz + dq * H_);
                ulonglong2 wn = *(const ulonglong2*)(Dn + dq * H_);
                const float* xb = &dec_s[tb][0][kh * 16 + dq * 4];
#pragma unroll
                for (int b = 0; b < 8; b++) {
                    ulonglong2 x2 = *(const ulonglong2*)(xb + b * D_);
                    fma2(ar[b], wr.x, x2.x); fma2(ar[b], wr.y, x2.y);
                    fma2(az[b], wz.x, x2.x); fma2(az[b], wz.y, x2.y);
                    fma2(an[b], wn.x, x2.x); fma2(an[b], wn.y, x2.y);
                }
            }
        }

        // prefetch next decoder input
        float vnext = 0.f;
        if (tid < 256 && t + 1 < T_) {
            int b = tid >> 5, d = tid & 31;
            vnext = x_current[((b0 + b) * T_ + t) * D_ + d];
        }

        // ---- exchange: collapsed partials for the other half's 4 batches ----
#pragma unroll
        for (int i = 0; i < 4; i++) {
            int b = obh * 4 + i;
            xch[kh][i][j]      = col2(ar[b]);
            xch[kh][4 + i][j]  = col2(az[b]);
            xch[kh][8 + i][j]  = anf[b];
            xch[kh][12 + i][j] = col2(an[b]);
        }
        __syncthreads();                                  // A: xch ready, h_s reads done

        // ---- combine + epilogue for my 4 batches ----
        float p[4];
#pragma unroll
        for (int i = 0; i < 4; i++) {
            int b = kh * 4 + i;
            float arf = col2(ar[b]) + xch[obh][i][j];
            float azf = col2(az[b]) + xch[obh][4 + i][j];
            float ahf = anf[b]      + xch[obh][8 + i][j];
            float aif = col2(an[b]) + xch[obh][12 + i][j];
            float r = fsigmoid(arf);
            float u = fsigmoid(azf);
            float n = ftanh(aif + r * ahf);
            float hold = h_s[b][j];
            float hn = n + u * (hold - n);
            h_s[b][j] = hn;
            p[i] = fcw * hn;
        }
        if (tid < 256 && t + 1 < T_) {
            int b = tid >> 5, d = tid & 31;
            dec_s[tb ^ 1][b][d] = vnext;
        }

        // fc reduction
#pragma unroll
        for (int i = 0; i < 4; i++) {
#pragma unroll
            for (int off = 16; off > 0; off >>= 1)
                p[i] += __shfl_down_sync(0xffffffffu, p[i], off);
        }
        if (lane == 0) {
#pragma unroll
            for (int i = 0; i < 4; i++) red_s[warp][i] = p[i];
        }
        __syncthreads();                                  // B: red_s/h_s(new)/dec_s ready

        if (tid < 8) {
            int w0 = (tid < 4) ? 0 : 8;
            int col = tid & 3;
            float s = fcbv;
#pragma unroll
            for (int w = 0; w < 8; w++) s += red_s[w0 + w][col];
            out[((b0 + tid) * T_ + t) * D_ + head] = s;
        }
    }
}

// ---------------- launch ----------------
extern "C" void kernel_launch(void* const* d_in, const int* in_sizes, int n_in,
                              void* d_out, int out_size) {
    (void)in_sizes; (void)n_in; (void)out_size;
    const float* x_past    = (const float*)d_in[0];
    const float* x_current = (const float*)d_in[1];
    const float* eps       = (const float*)d_in[2];
    const float* enc_Wih   = (const float*)d_in[3];
    const float* enc_bih   = (const float*)d_in[4];
    const float* enc_Whh   = (const float*)d_in[5];
    const float* enc_bhh   = (const float*)d_in[6];
    const float* enc_mu_w  = (const float*)d_in[7];
    const float* enc_mu_b  = (const float*)d_in[8];
    const float* enc_ls_w  = (const float*)d_in[9];
    const float* enc_ls_b  = (const float*)d_in[10];
    const float* refc_w    = (const float*)d_in[11];
    const float* refc_b    = (const float*)d_in[12];
    const float* Win       = (const float*)d_in[13];
    const float* h_Wih     = (const float*)d_in[14];
    const float* h_bih     = (const float*)d_in[15];
    const float* h_Whh     = (const float*)d_in[16];
    const float* h_bhh     = (const float*)d_in[17];
    const float* fc_w      = (const float*)d_in[18];
    const float* fc_b      = (const float*)d_in[19];
    float* out = (float*)d_out;

    prep_kernel<<<1041, 256>>>(h_Whh, h_Wih, enc_Whh, enc_Wih, enc_mu_w, enc_ls_w, refc_w);
    weff_kernel<<<dim3(32, 3), 256>>>(Win);
    encoder_kernel<<<32, 1024>>>(x_past, enc_bih, enc_bhh, eps, enc_mu_b, enc_ls_b,
                                 refc_b, out);
    decoder_kernel<<<dim3(32, 4), 512>>>(x_past, x_current, h_bih, h_bhh,
                                         fc_w, fc_b, out);
}